// round 1
// baseline (speedup 1.0000x reference)
#include <cuda_runtime.h>
#include <cuda_bf16.h>

#define D 512
#define P_MAX 32768
#define WARPS_PER_BLOCK 8
#define THREADS (WARPS_PER_BLOCK * 32)
#define NBLOCKS (P_MAX / WARPS_PER_BLOCK)   // 4096

// Per-block partials (no device allocation allowed -> __device__ globals).
__device__ float g_partial_sum[NBLOCKS];
__device__ float g_partial_cnt[NBLOCKS];

__global__ __launch_bounds__(THREADS)
void pair_kernel(const float* __restrict__ vf,
                 const int* __restrict__ idx1,
                 const int* __restrict__ idx2,
                 const float* __restrict__ time_gaps,
                 int P)
{
    const int warp = threadIdx.x >> 5;
    const int lane = threadIdx.x & 31;
    const int p = blockIdx.x * WARPS_PER_BLOCK + warp;

    float term = 0.0f;   // mask * (1 - cos)
    float cnt  = 0.0f;

    if (p < P) {
        float tg = __ldg(&time_gaps[p]);
        if (tg <= 2.0f) {
            const int i1 = __ldg(&idx1[p]);
            const int i2 = __ldg(&idx2[p]);
            const float4* ri = reinterpret_cast<const float4*>(vf + (size_t)i1 * D);
            const float4* rj = reinterpret_cast<const float4*>(vf + (size_t)i2 * D);

            float dot = 0.0f, a2 = 0.0f, b2 = 0.0f;
            #pragma unroll
            for (int k = 0; k < 4; k++) {
                float4 a = ri[lane + 32 * k];
                float4 b = rj[lane + 32 * k];
                dot += a.x * b.x + a.y * b.y + a.z * b.z + a.w * b.w;
                a2  += a.x * a.x + a.y * a.y + a.z * a.z + a.w * a.w;
                b2  += b.x * b.x + b.y * b.y + b.z * b.z + b.w * b.w;
            }
            // warp butterfly reduce (3 values)
            #pragma unroll
            for (int off = 16; off > 0; off >>= 1) {
                dot += __shfl_xor_sync(0xFFFFFFFFu, dot, off);
                a2  += __shfl_xor_sync(0xFFFFFFFFu, a2,  off);
                b2  += __shfl_xor_sync(0xFFFFFFFFu, b2,  off);
            }
            float denom = fmaxf(sqrtf(a2) * sqrtf(b2), 1e-8f);
            float cosv  = dot / denom;
            term = 1.0f - cosv;
            cnt  = 1.0f;
        }
    }

    // lane 0 of each warp deposits; block tree-reduce in shared (fixed order)
    __shared__ float s_sum[WARPS_PER_BLOCK];
    __shared__ float s_cnt[WARPS_PER_BLOCK];
    if (lane == 0) { s_sum[warp] = term; s_cnt[warp] = cnt; }
    __syncthreads();
    if (threadIdx.x == 0) {
        float ts = 0.0f, tc = 0.0f;
        #pragma unroll
        for (int w = 0; w < WARPS_PER_BLOCK; w++) { ts += s_sum[w]; tc += s_cnt[w]; }
        g_partial_sum[blockIdx.x] = ts;
        g_partial_cnt[blockIdx.x] = tc;
    }
}

__global__ __launch_bounds__(1024)
void finalize_kernel(const int* __restrict__ cur_epoch,
                     const int* __restrict__ tot_epochs,
                     float* __restrict__ out)
{
    __shared__ float s_sum[1024];
    __shared__ float s_cnt[1024];
    const int tid = threadIdx.x;

    float s = 0.0f, c = 0.0f;
    for (int i = tid; i < NBLOCKS; i += 1024) {
        s += g_partial_sum[i];
        c += g_partial_cnt[i];
    }
    s_sum[tid] = s;
    s_cnt[tid] = c;
    __syncthreads();

    #pragma unroll
    for (int stride = 512; stride > 0; stride >>= 1) {
        if (tid < stride) {
            s_sum[tid] += s_sum[tid + stride];
            s_cnt[tid] += s_cnt[tid + stride];
        }
        __syncthreads();
    }

    if (tid == 0) {
        int ce = cur_epoch[0];
        int te = tot_epochs[0];
        float progress = (float)ce / (float)(te > 1 ? te : 1);
        float lam = 0.1f + (0.3f - 0.1f) * progress;
        float total = s_sum[0];
        float npairs = s_cnt[0];
        float loss = (npairs > 0.0f) ? lam * total / fmaxf(npairs, 1.0f) : 0.0f;
        out[0] = loss;
    }
}

extern "C" void kernel_launch(void* const* d_in, const int* in_sizes, int n_in,
                              void* d_out, int out_size)
{
    const float* vf        = (const float*)d_in[0];
    const int*   idx1      = (const int*)d_in[1];
    const int*   idx2      = (const int*)d_in[2];
    const float* time_gaps = (const float*)d_in[3];
    const int*   cur_epoch = (const int*)d_in[4];
    const int*   tot_epoch = (const int*)d_in[5];
    float*       out       = (float*)d_out;

    const int P = in_sizes[3];  // number of pairs

    int nblocks = (P + WARPS_PER_BLOCK - 1) / WARPS_PER_BLOCK;
    pair_kernel<<<nblocks, THREADS>>>(vf, idx1, idx2, time_gaps, P);
    finalize_kernel<<<1, 1024>>>(cur_epoch, tot_epoch, out);
}

// round 3
// speedup vs baseline: 1.0865x; 1.0865x over previous
#include <cuda_runtime.h>
#include <cuda_bf16.h>

#define D 512
#define NB 512                 // grid size (blocks)
#define WARPS_PER_BLOCK 8
#define THREADS (WARPS_PER_BLOCK * 32)

// Scratch (no device allocation allowed -> __device__ globals).
__device__ float g_partial_sum[NB];
__device__ float g_partial_cnt[NB];
__device__ unsigned int g_ticket = 0;   // zero-init; reset by finalizing block each launch

__global__ __launch_bounds__(THREADS)
void fused_loss_kernel(const float* __restrict__ vf,
                       const int* __restrict__ idx1,
                       const int* __restrict__ idx2,
                       const float* __restrict__ time_gaps,
                       const int* __restrict__ cur_epoch,
                       const int* __restrict__ tot_epochs,
                       float* __restrict__ out,
                       int P)
{
    const int warp = threadIdx.x >> 5;
    const int lane = threadIdx.x & 31;
    const int gwarp = blockIdx.x * WARPS_PER_BLOCK + warp;
    const int nwarps = gridDim.x * WARPS_PER_BLOCK;

    float wsum = 0.0f;   // sum of mask*(1-cos) over this warp's pairs
    float wcnt = 0.0f;

    for (int p = gwarp; p < P; p += nwarps) {
        float tg = __ldg(&time_gaps[p]);
        if (tg <= 2.0f) {
            const int i1 = __ldg(&idx1[p]);
            const int i2 = __ldg(&idx2[p]);
            const float4* ri = reinterpret_cast<const float4*>(vf + (size_t)i1 * D);
            const float4* rj = reinterpret_cast<const float4*>(vf + (size_t)i2 * D);

            float dot = 0.0f, a2 = 0.0f, b2 = 0.0f;
            #pragma unroll
            for (int k = 0; k < 4; k++) {
                float4 a = ri[lane + 32 * k];
                float4 b = rj[lane + 32 * k];
                dot += a.x * b.x + a.y * b.y + a.z * b.z + a.w * b.w;
                a2  += a.x * a.x + a.y * a.y + a.z * a.z + a.w * a.w;
                b2  += b.x * b.x + b.y * b.y + b.z * b.z + b.w * b.w;
            }
            #pragma unroll
            for (int off = 16; off > 0; off >>= 1) {
                dot += __shfl_xor_sync(0xFFFFFFFFu, dot, off);
                a2  += __shfl_xor_sync(0xFFFFFFFFu, a2,  off);
                b2  += __shfl_xor_sync(0xFFFFFFFFu, b2,  off);
            }
            float denom = fmaxf(sqrtf(a2) * sqrtf(b2), 1e-8f);
            wsum += 1.0f - dot / denom;
            wcnt += 1.0f;
        }
    }

    // Per-block reduce (fixed order -> deterministic)
    __shared__ float s_sum[WARPS_PER_BLOCK];
    __shared__ float s_cnt[WARPS_PER_BLOCK];
    __shared__ bool  s_last;
    if (lane == 0) { s_sum[warp] = wsum; s_cnt[warp] = wcnt; }
    __syncthreads();
    if (threadIdx.x == 0) {
        float ts = 0.0f, tc = 0.0f;
        #pragma unroll
        for (int w = 0; w < WARPS_PER_BLOCK; w++) { ts += s_sum[w]; tc += s_cnt[w]; }
        g_partial_sum[blockIdx.x] = ts;
        g_partial_cnt[blockIdx.x] = tc;
        __threadfence();
        unsigned int t = atomicAdd(&g_ticket, 1u);
        s_last = (t == gridDim.x - 1);
    }
    __syncthreads();

    if (!s_last) return;

    // Last-arriving block: all prior blocks' partials are visible
    // (their threadfence happened-before their atomicAdd, which
    // happened-before ours returned gridDim.x-1).
    __threadfence();

    __shared__ float f_sum[THREADS];
    __shared__ float f_cnt[THREADS];
    float s = 0.0f, c = 0.0f;
    #pragma unroll
    for (int i = threadIdx.x; i < NB; i += THREADS) {
        s += g_partial_sum[i];
        c += g_partial_cnt[i];
    }
    f_sum[threadIdx.x] = s;
    f_cnt[threadIdx.x] = c;
    __syncthreads();
    #pragma unroll
    for (int stride = THREADS / 2; stride > 0; stride >>= 1) {
        if (threadIdx.x < stride) {
            f_sum[threadIdx.x] += f_sum[threadIdx.x + stride];
            f_cnt[threadIdx.x] += f_cnt[threadIdx.x + stride];
        }
        __syncthreads();
    }

    if (threadIdx.x == 0) {
        int ce = cur_epoch[0];
        int te = tot_epochs[0];
        float progress = (float)ce / (float)(te > 1 ? te : 1);
        float lam = 0.1f + (0.3f - 0.1f) * progress;
        float total = f_sum[0];
        float npairs = f_cnt[0];
        out[0] = (npairs > 0.0f) ? lam * total / fmaxf(npairs, 1.0f) : 0.0f;
        g_ticket = 0;   // reset for next (graph-replayed) launch
    }
}

extern "C" void kernel_launch(void* const* d_in, const int* in_sizes, int n_in,
                              void* d_out, int out_size)
{
    const float* vf        = (const float*)d_in[0];
    const int*   idx1      = (const int*)d_in[1];
    const int*   idx2      = (const int*)d_in[2];
    const float* time_gaps = (const float*)d_in[3];
    const int*   cur_epoch = (const int*)d_in[4];
    const int*   tot_epoch = (const int*)d_in[5];
    float*       out       = (float*)d_out;

    const int P = in_sizes[3];

    fused_loss_kernel<<<NB, THREADS>>>(vf, idx1, idx2, time_gaps,
                                       cur_epoch, tot_epoch, out, P);
}

// round 4
// speedup vs baseline: 1.0934x; 1.0064x over previous
#include <cuda_runtime.h>
#include <cuda_bf16.h>

#define D 512
#define NB 512                 // grid size (blocks)
#define WARPS_PER_BLOCK 8
#define THREADS (WARPS_PER_BLOCK * 32)

// Scratch (no device allocation allowed -> __device__ globals).
__device__ float g_partial_sum[NB];
__device__ float g_partial_cnt[NB];
__device__ unsigned int g_ticket = 0;   // zero-init; reset by finalizing block each launch

__global__ __launch_bounds__(THREADS)
void fused_loss_kernel(const float* __restrict__ vf,
                       const int* __restrict__ idx1,
                       const int* __restrict__ idx2,
                       const float* __restrict__ time_gaps,
                       const int* __restrict__ cur_epoch,
                       const int* __restrict__ tot_epochs,
                       float* __restrict__ out,
                       int P)
{
    const int warp = threadIdx.x >> 5;
    const int lane = threadIdx.x & 31;
    const int gwarp = blockIdx.x * WARPS_PER_BLOCK + warp;
    const int nwarps = gridDim.x * WARPS_PER_BLOCK;

    float wsum = 0.0f;   // sum of mask*(1-cos) over this warp's pairs
    float wcnt = 0.0f;

    for (int p = gwarp; p < P; p += nwarps) {
        float tg = __ldg(&time_gaps[p]);
        if (tg <= 2.0f) {
            const int i1 = __ldg(&idx1[p]);
            const int i2 = __ldg(&idx2[p]);
            const float4* ri = reinterpret_cast<const float4*>(vf + (size_t)i1 * D);
            const float4* rj = reinterpret_cast<const float4*>(vf + (size_t)i2 * D);

            float dot = 0.0f, a2 = 0.0f, b2 = 0.0f;
            #pragma unroll
            for (int k = 0; k < 4; k++) {
                float4 a = ri[lane + 32 * k];
                float4 b = rj[lane + 32 * k];
                dot += a.x * b.x + a.y * b.y + a.z * b.z + a.w * b.w;
                a2  += a.x * a.x + a.y * a.y + a.z * a.z + a.w * a.w;
                b2  += b.x * b.x + b.y * b.y + b.z * b.z + b.w * b.w;
            }
            #pragma unroll
            for (int off = 16; off > 0; off >>= 1) {
                dot += __shfl_xor_sync(0xFFFFFFFFu, dot, off);
                a2  += __shfl_xor_sync(0xFFFFFFFFu, a2,  off);
                b2  += __shfl_xor_sync(0xFFFFFFFFu, b2,  off);
            }
            float denom = fmaxf(sqrtf(a2) * sqrtf(b2), 1e-8f);
            wsum += 1.0f - dot / denom;
            wcnt += 1.0f;
        }
    }

    // Per-block reduce (fixed order -> deterministic)
    __shared__ float s_sum[WARPS_PER_BLOCK];
    __shared__ float s_cnt[WARPS_PER_BLOCK];
    __shared__ bool  s_last;
    if (lane == 0) { s_sum[warp] = wsum; s_cnt[warp] = wcnt; }
    __syncthreads();
    if (threadIdx.x == 0) {
        float ts = 0.0f, tc = 0.0f;
        #pragma unroll
        for (int w = 0; w < WARPS_PER_BLOCK; w++) { ts += s_sum[w]; tc += s_cnt[w]; }
        g_partial_sum[blockIdx.x] = ts;
        g_partial_cnt[blockIdx.x] = tc;
        __threadfence();
        unsigned int t = atomicAdd(&g_ticket, 1u);
        s_last = (t == gridDim.x - 1);
    }
    __syncthreads();

    if (!s_last) return;

    // Last-arriving block: all prior blocks' partials are visible
    // (their threadfence happened-before their atomicAdd, which
    // happened-before ours returned gridDim.x-1).
    __threadfence();

    __shared__ float f_sum[THREADS];
    __shared__ float f_cnt[THREADS];
    float s = 0.0f, c = 0.0f;
    #pragma unroll
    for (int i = threadIdx.x; i < NB; i += THREADS) {
        s += g_partial_sum[i];
        c += g_partial_cnt[i];
    }
    f_sum[threadIdx.x] = s;
    f_cnt[threadIdx.x] = c;
    __syncthreads();
    #pragma unroll
    for (int stride = THREADS / 2; stride > 0; stride >>= 1) {
        if (threadIdx.x < stride) {
            f_sum[threadIdx.x] += f_sum[threadIdx.x + stride];
            f_cnt[threadIdx.x] += f_cnt[threadIdx.x + stride];
        }
        __syncthreads();
    }

    if (threadIdx.x == 0) {
        int ce = cur_epoch[0];
        int te = tot_epochs[0];
        float progress = (float)ce / (float)(te > 1 ? te : 1);
        float lam = 0.1f + (0.3f - 0.1f) * progress;
        float total = f_sum[0];
        float npairs = f_cnt[0];
        out[0] = (npairs > 0.0f) ? lam * total / fmaxf(npairs, 1.0f) : 0.0f;
        g_ticket = 0;   // reset for next (graph-replayed) launch
    }
}

extern "C" void kernel_launch(void* const* d_in, const int* in_sizes, int n_in,
                              void* d_out, int out_size)
{
    const float* vf        = (const float*)d_in[0];
    const int*   idx1      = (const int*)d_in[1];
    const int*   idx2      = (const int*)d_in[2];
    const float* time_gaps = (const float*)d_in[3];
    const int*   cur_epoch = (const int*)d_in[4];
    const int*   tot_epoch = (const int*)d_in[5];
    float*       out       = (float*)d_out;

    const int P = in_sizes[3];

    fused_loss_kernel<<<NB, THREADS>>>(vf, idx1, idx2, time_gaps,
                                       cur_epoch, tot_epoch, out, P);
}